// round 15
// baseline (speedup 1.0000x reference)
#include <cuda_runtime.h>
#include <math.h>
#include <stdint.h>

#define NTOK 4096
#define DM   512
#define EX   32
#define HH   128
#define TOPK 4
#define NK   (NTOK*TOPK)
#define MT   32     // expert token tile
#define NBLK 128    // score/fill block count
#define WN   (EX*DM*HH)

// ---------------- device scratch (no allocs allowed) ----------------
__device__ int   g_bcnt[NBLK * EX];
__device__ int   g_offsets[EX + 1];
__device__ int   g_fillbase[NBLK * EX];
__device__ int   g_tokcnt[NTOK];
__device__ int   g_route_e[NK];
__device__ float g_route_g[NK];
__device__ int   g_perm_nk[NK];
__device__ float g_perm_g[NK];
__device__ float g_buf[NK * DM];        // 32 MB partials indexed by (n*4+k)
__device__ float g_xr[NTOK * DM];       // tf32-rounded x
__device__ float g_w1r[WN];             // tf32-rounded w1 [E,D,H]
__device__ float g_w2r[WN];             // tf32-rounded w2 [E,H,D]

// ---------------- helpers ----------------
__device__ __forceinline__ uint32_t smem_u32(const void* p) {
    uint32_t a;
    asm("{ .reg .u64 t; cvta.to.shared.u64 t, %1; cvt.u32.u64 %0, t; }" : "=r"(a) : "l"(p));
    return a;
}
__device__ __forceinline__ float to_tf32(float x) {
    float r;
    asm("cvt.rna.tf32.f32 %0, %1;" : "=f"(r) : "f"(x));
    return r;
}
__device__ __forceinline__ float4 round4(float4 v) {
    v.x = to_tf32(v.x); v.y = to_tf32(v.y); v.z = to_tf32(v.z); v.w = to_tf32(v.w);
    return v;
}
__device__ __forceinline__ void mma_tf32(float* c, const uint32_t* a, uint32_t b0, uint32_t b1) {
    asm volatile(
        "mma.sync.aligned.m16n8k8.row.col.f32.tf32.tf32.f32 "
        "{%0,%1,%2,%3}, {%4,%5,%6,%7}, {%8,%9}, {%0,%1,%2,%3};"
        : "+f"(c[0]), "+f"(c[1]), "+f"(c[2]), "+f"(c[3])
        : "r"(a[0]), "r"(a[1]), "r"(a[2]), "r"(a[3]), "r"(b0), "r"(b1));
}
__device__ __forceinline__ void ldsm_x4(uint32_t* d, uint32_t addr) {
    asm volatile("ldmatrix.sync.aligned.m8n8.x4.shared.b16 {%0,%1,%2,%3}, [%4];"
                 : "=r"(d[0]), "=r"(d[1]), "=r"(d[2]), "=r"(d[3]) : "r"(addr));
}
__device__ __forceinline__ void cpa16(uint32_t s, const void* g) {
    asm volatile("cp.async.ca.shared.global [%0], [%1], 16;" :: "r"(s), "l"(g));
}
#define CPA_COMMIT() asm volatile("cp.async.commit_group;" ::: "memory")
#define CPA_WAIT0()  asm volatile("cp.async.wait_group 0;" ::: "memory")

// ---------------- routing: scores + top-4 + x/w tf32 pre-rounding ----------------
__global__ void __launch_bounds__(256) k_score(const float* __restrict__ x,
                                               const float* __restrict__ sel,
                                               const float* __restrict__ w1,
                                               const float* __restrict__ w2) {
    __shared__ float Xs[32][36];
    __shared__ float Bs[32][36];
    __shared__ float Ss[32][36];
    __shared__ int   scnt[EX];
    int tid = threadIdx.x;
    int n0 = blockIdx.x * 32;
    int trow = tid >> 3;
    int tc = (tid & 7) * 4;
    if (tid < EX) scnt[tid] = 0;
    if (tid < 32) g_tokcnt[n0 + tid] = 0;
    float acc[4] = {0.f, 0.f, 0.f, 0.f};

    for (int k0 = 0; k0 < DM; k0 += 32) {
        {
            int r = tid >> 3, c = (tid & 7) * 4;
            size_t gi = (size_t)(n0 + r) * DM + k0 + c;
            float4 v = *(const float4*)(x + gi);
            *(float4*)&Xs[r][c] = v;
            *(float4*)(g_xr + gi) = round4(v);
        }
        {
            int e = tid >> 3, kk = (tid & 7) * 4;
            float4 v = *(const float4*)(sel + (size_t)e * DM + k0 + kk);
            Bs[kk][e] = v.x; Bs[kk + 1][e] = v.y; Bs[kk + 2][e] = v.z; Bs[kk + 3][e] = v.w;
        }
        __syncthreads();
#pragma unroll
        for (int kk = 0; kk < 32; kk++) {
            float a = Xs[trow][kk];
            float4 b = *(float4*)&Bs[kk][tc];
            acc[0] += a * b.x; acc[1] += a * b.y; acc[2] += a * b.z; acc[3] += a * b.w;
        }
        __syncthreads();
    }
    *(float4*)&Ss[trow][tc] = make_float4(acc[0], acc[1], acc[2], acc[3]);
    __syncthreads();

    if (tid < 32) {
        int n = n0 + tid;
        float s[EX];
#pragma unroll
        for (int e = 0; e < EX; e++) s[e] = Ss[tid][e];
        for (int k = 0; k < TOPK; k++) {
            float best = -INFINITY; int bi = 0;
#pragma unroll
            for (int e = 0; e < EX; e++)
                if (s[e] > best) { best = s[e]; bi = e; }
            s[bi] = -INFINITY;
            g_route_e[n * TOPK + k] = bi;
            g_route_g[n * TOPK + k] = 1.f / (1.f + expf(-best));
            atomicAdd(&scnt[bi], 1);
        }
    }
    __syncthreads();
    if (tid < EX) g_bcnt[blockIdx.x * EX + tid] = scnt[tid];

    // ---- distributed weight rounding: 32 float4 per thread, coalesced ----
    {
        int q = blockIdx.x * 256 + tid;
#pragma unroll 4
        for (int i = 0; i < 32; i++) {
            int idx = (q + i * NBLK * 256) * 4;
            if (idx < WN)
                *(float4*)(g_w1r + idx) = round4(*(const float4*)(w1 + idx));
            else
                *(float4*)(g_w2r + idx - WN) = round4(*(const float4*)(w2 + idx - WN));
        }
    }
}

// ---------------- scan: offsets + per-fill-block bases (1 warp) ----------------
__global__ void k_scan() {
    int lane = threadIdx.x;
    int tot = 0;
    for (int b = 0; b < NBLK; b++) tot += g_bcnt[b * EX + lane];
    int s = tot;
#pragma unroll
    for (int off = 1; off < 32; off <<= 1) {
        int v = __shfl_up_sync(0xffffffffu, s, off);
        if (lane >= off) s += v;
    }
    int excl = s - tot;
    g_offsets[lane] = excl;
    if (lane == EX - 1) g_offsets[EX] = s;
    int run = excl;
    for (int b = 0; b < NBLK; b++) {
        g_fillbase[b * EX + lane] = run;
        run += g_bcnt[b * EX + lane];
    }
}

// ---------------- fill: per-expert token lists ----------------
__global__ void __launch_bounds__(128) k_fill() {
    __shared__ int sbase[EX], scnt[EX];
    int tid = threadIdx.x;
    if (tid < 32) {
        sbase[tid] = g_fillbase[blockIdx.x * EX + tid];
        scnt[tid] = 0;
    }
    __syncthreads();
    int t = blockIdx.x * 128 + tid;
    int e = g_route_e[t];
    int lp = atomicAdd(&scnt[e], 1);
    int p = sbase[e] + lp;
    g_perm_nk[p] = t;
    g_perm_g[p] = g_route_g[t];
}

// ---------------- expert MLP: MT=32, tf32 + ldmatrix + cp.async.ca, 3 blocks/SM ----------------
#define AS 36
#define BS 136
#define HS 132
#define A_BYTES (32*AS*4)    // 4608 per stage
#define B_BYTES (32*BS*4)    // 17408 per stage
#define OFF_A 0              // 2 stages: [0, 9216)
#define OFF_B 9216           // 2 stages: [9216, 44032)
#define OFF_H 44032          // [44032, 60928)
#define OFF_NK   60928
#define OFF_NROW 61056
#define OFF_GATE 61184
#define SMEM_EXPERT 61312    // 3 blocks/SM = 184 KB

__global__ void __launch_bounds__(256, 3) k_expert(float* __restrict__ y) {
    extern __shared__ char sm[];
    __shared__ int winners[MT];
    __shared__ int nwin;
    int tid = threadIdx.x, lane = tid & 31, wid = tid >> 5;
    int e = blockIdx.y;

    int off0 = g_offsets[e], off1 = g_offsets[e + 1];
    int base = off0 + blockIdx.x * MT;
    if (base >= off1) return;
    int cnt = min(MT, off1 - base);

    float* Hsm = (float*)(sm + OFF_H);
    int*   nks   = (int*)(sm + OFF_NK);
    int*   nrow  = (int*)(sm + OFF_NROW);
    float* gates = (float*)(sm + OFF_GATE);
    if (tid == 0) nwin = 0;
    if (tid < MT) {
        if (tid < cnt) {
            int nk = g_perm_nk[base + tid];
            nks[tid] = nk; nrow[tid] = nk >> 2; gates[tid] = g_perm_g[base + tid];
        } else {
            nks[tid] = 0; nrow[tid] = 0; gates[tid] = 0.f;
        }
    }
    __syncthreads();

    const float* w1e = g_w1r + (size_t)e * DM * HH;   // [D,H]
    const float* w2e = g_w2r + (size_t)e * HH * DM;   // [H,D]

    int g = lane >> 2, t4 = lane & 3;
    int ncol0 = wid * 16;                 // 8 warps x 16-col tiles, all 32 rows
    int Lrow = (lane & 7) + ((lane >> 3) & 1) * 8;
    int Lcol = (lane >> 4) * 4;

    uint32_t smb = smem_u32(sm);
    uint32_t smbA = smb + OFF_A, smbB = smb + OFF_B, smbH = smb + OFF_H;

    // staging coords
    int ar0 = tid >> 3, ac0 = (tid & 7) * 4;          // A: 32x32, 1 float4/thread
    int br0 = tid >> 5, bc0 = (tid & 31) * 4;         // B: 32x128, 4 float4/thread
    const float* pA = g_xr + (size_t)nrow[ar0] * DM + ac0;
    const float* pB1 = w1e + (size_t)br0 * HH + bc0;
    uint32_t sA = smbA + (uint32_t)(ar0 * AS + ac0) * 4;
    uint32_t sB = smbB + (uint32_t)(br0 * BS + bc0) * 4;

    // ---- GEMM1: H[32,128] = X*W1, 16 chunks of K=32, cp.async 2-stage ----
    float c1[2][2][4];
#pragma unroll
    for (int mi = 0; mi < 2; mi++)
#pragma unroll
        for (int ni = 0; ni < 2; ni++)
#pragma unroll
            for (int j = 0; j < 4; j++) c1[mi][ni][j] = 0.f;

    cpa16(sA, pA);
#pragma unroll
    for (int i = 0; i < 4; i++) cpa16(sB + i * 8 * BS * 4, pB1 + i * 8 * HH);
    CPA_COMMIT();

    int p = 0;
    for (int kc = 0; kc < 16; kc++) {
        CPA_WAIT0();
        __syncthreads();
        if (kc < 15) {
            int k0 = (kc + 1) * 32;
            int q = 1 - p;
            cpa16(sA + q * A_BYTES, pA + k0);
#pragma unroll
            for (int i = 0; i < 4; i++)
                cpa16(sB + q * B_BYTES + i * 8 * BS * 4, pB1 + (size_t)(k0 + i * 8) * HH);
            CPA_COMMIT();
        }
        uint32_t aBase = smbA + (uint32_t)p * A_BYTES;
        const float* Bsh = (const float*)(sm + OFF_B + p * B_BYTES);
#pragma unroll
        for (int ks = 0; ks < 4; ks++) {
            int kk = ks * 8;
            uint32_t a[2][4];
#pragma unroll
            for (int mi = 0; mi < 2; mi++)
                ldsm_x4(a[mi], aBase + (uint32_t)((mi * 16 + Lrow) * AS + Lcol + kk) * 4);
#pragma unroll
            for (int ni = 0; ni < 2; ni++) {
                int n = ncol0 + ni * 8;
                uint32_t b0 = __float_as_uint(Bsh[(kk + t4) * BS + n + g]);
                uint32_t b1 = __float_as_uint(Bsh[(kk + t4 + 4) * BS + n + g]);
#pragma unroll
                for (int mi = 0; mi < 2; mi++)
                    mma_tf32(c1[mi][ni], a[mi], b0, b1);
            }
        }
        p ^= 1;
    }
    __syncthreads();   // all warps done with A/B stages

    // start GEMM2's first B chunk (stage 0 free; overlaps H writes)
    const float* pB2 = w2e + (size_t)br0 * DM + bc0;
#pragma unroll
    for (int i = 0; i < 4; i++) cpa16(sB + i * 8 * BS * 4, pB2 + i * 8 * DM);
    CPA_COMMIT();

    // ---- H = tf32(relu(.)*gate) -> SMEM [32m][128k] ----
#pragma unroll
    for (int mi = 0; mi < 2; mi++) {
        int rA = mi * 16 + g;
        float gA = gates[rA], gB = gates[rA + 8];
#pragma unroll
        for (int ni = 0; ni < 2; ni++) {
            int col = ncol0 + ni * 8 + t4 * 2;
            float2 hA, hB;
            hA.x = to_tf32(fmaxf(c1[mi][ni][0], 0.f) * gA);
            hA.y = to_tf32(fmaxf(c1[mi][ni][1], 0.f) * gA);
            hB.x = to_tf32(fmaxf(c1[mi][ni][2], 0.f) * gB);
            hB.y = to_tf32(fmaxf(c1[mi][ni][3], 0.f) * gB);
            *(float2*)&Hsm[rA * HS + col] = hA;
            *(float2*)&Hsm[(rA + 8) * HS + col] = hB;
        }
    }
    __syncthreads();

    // ---- GEMM2: Y[32,512] = H[32,128] * W2[128,512]; 16 chunks = (v, kch) ----
    float c2[2][2][4];
#pragma unroll
    for (int mi = 0; mi < 2; mi++)
#pragma unroll
        for (int ni = 0; ni < 2; ni++)
#pragma unroll
            for (int j = 0; j < 4; j++) c2[mi][ni][j] = 0.f;

    p = 0;
    for (int c = 0; c < 16; c++) {
        int v = c >> 2, kch = c & 3;
        CPA_WAIT0();
        __syncthreads();
        if (c < 15) {
            int vn = (c + 1) >> 2, kn = (c + 1) & 3;
            int q = 1 - p;
#pragma unroll
            for (int i = 0; i < 4; i++)
                cpa16(sB + q * B_BYTES + i * 8 * BS * 4,
                      pB2 + (size_t)(kn * 32 + i * 8) * DM + vn * 128);
            CPA_COMMIT();
        }
        const float* Bsh = (const float*)(sm + OFF_B + p * B_BYTES);
#pragma unroll
        for (int ks = 0; ks < 4; ks++) {
            int kh = kch * 32 + ks * 8;
            int kk = ks * 8;
            uint32_t a[2][4];
#pragma unroll
            for (int mi = 0; mi < 2; mi++)
                ldsm_x4(a[mi], smbH + (uint32_t)((mi * 16 + Lrow) * HS + Lcol + kh) * 4);
#pragma unroll
            for (int ni = 0; ni < 2; ni++) {
                int n = ncol0 + ni * 8;
                uint32_t b0 = __float_as_uint(Bsh[(kk + t4) * BS + n + g]);
                uint32_t b1 = __float_as_uint(Bsh[(kk + t4 + 4) * BS + n + g]);
#pragma unroll
                for (int mi = 0; mi < 2; mi++)
                    mma_tf32(c2[mi][ni], a[mi], b0, b1);
            }
        }
        p ^= 1;

        if (kch == 3) {
            int v0 = v * 128;
#pragma unroll
            for (int mi = 0; mi < 2; mi++) {
                int rA = mi * 16 + g;
                int rB = rA + 8;
#pragma unroll
                for (int ni = 0; ni < 2; ni++) {
                    int col = v0 + ncol0 + ni * 8 + t4 * 2;
                    if (rA < cnt) {
                        float2 o0; o0.x = c2[mi][ni][0]; o0.y = c2[mi][ni][1];
                        *(float2*)(g_buf + (size_t)nks[rA] * DM + col) = o0;
                    }
                    if (rB < cnt) {
                        float2 o1; o1.x = c2[mi][ni][2]; o1.y = c2[mi][ni][3];
                        *(float2*)(g_buf + (size_t)nks[rB] * DM + col) = o1;
                    }
                    c2[mi][ni][0] = 0.f; c2[mi][ni][1] = 0.f;
                    c2[mi][ni][2] = 0.f; c2[mi][ni][3] = 0.f;
                }
            }
        }
    }

    // ---- fused reduce: last completer sums a token's 4 partials ----
    __syncthreads();
    __threadfence();
    if (tid < cnt) {
        int n = nrow[tid];
        int old = atomicAdd(&g_tokcnt[n], 1);
        if (old == 3) {
            int w = atomicAdd(&nwin, 1);
            winners[w] = n;
        }
    }
    __syncthreads();
    __threadfence();
    int nw = nwin;
    const float4* bb = (const float4*)g_buf;
    for (int i = tid; i < nw * 128; i += 256) {
        int n = winners[i >> 7], v4 = i & 127;
        size_t b0 = (size_t)(n * 4) * 128 + v4;
        float4 r0 = bb[b0];
        float4 r1 = bb[b0 + 128];
        float4 r2 = bb[b0 + 256];
        float4 r3 = bb[b0 + 384];
        float4 o;
        o.x = (r0.x + r1.x) + (r2.x + r3.x);
        o.y = (r0.y + r1.y) + (r2.y + r3.y);
        o.z = (r0.z + r1.z) + (r2.z + r3.z);
        o.w = (r0.w + r1.w) + (r2.w + r3.w);
        ((float4*)y)[(size_t)n * 128 + v4] = o;
    }
}

extern "C" void kernel_launch(void* const* d_in, const int* in_sizes, int n_in,
                              void* d_out, int out_size) {
    const float* x   = (const float*)d_in[0];
    const float* sel = (const float*)d_in[1];
    const float* w1  = (const float*)d_in[2];
    const float* w2  = (const float*)d_in[3];
    float* y = (float*)d_out;

    cudaFuncSetAttribute(k_expert, cudaFuncAttributeMaxDynamicSharedMemorySize, SMEM_EXPERT);

    k_score<<<NBLK, 256>>>(x, sel, w1, w2);
    k_scan<<<1, 32>>>();
    k_fill<<<NBLK, 128>>>();
    k_expert<<<dim3(32, EX), 256, SMEM_EXPERT>>>(y);
}

// round 17
// speedup vs baseline: 1.8170x; 1.8170x over previous
#include <cuda_runtime.h>
#include <math.h>
#include <stdint.h>

#define NTOK 4096
#define DM   512
#define EX   32
#define HH   128
#define TOPK 4
#define NK   (NTOK*TOPK)
#define MT   64     // expert token tile
#define NBLK 128    // score/fill block count

// ---------------- device scratch (no allocs allowed) ----------------
__device__ int   g_bcnt[NBLK * EX];
__device__ int   g_offsets[EX + 1];
__device__ int   g_fillbase[NBLK * EX];
__device__ int   g_tokcnt[NTOK];
__device__ int   g_route_e[NK];
__device__ float g_route_g[NK];
__device__ int   g_perm_nk[NK];
__device__ float g_perm_g[NK];
__device__ float g_buf[NK * DM];        // 32 MB partials indexed by (n*4+k)

// ---------------- helpers ----------------
__device__ __forceinline__ uint32_t smem_u32(const void* p) {
    uint32_t a;
    asm("{ .reg .u64 t; cvta.to.shared.u64 t, %1; cvt.u32.u64 %0, t; }" : "=r"(a) : "l"(p));
    return a;
}
__device__ __forceinline__ float to_tf32(float x) {
    float r;
    asm("cvt.rna.tf32.f32 %0, %1;" : "=f"(r) : "f"(x));
    return r;
}
__device__ __forceinline__ float4 round4(float4 v) {
    v.x = to_tf32(v.x); v.y = to_tf32(v.y); v.z = to_tf32(v.z); v.w = to_tf32(v.w);
    return v;
}
__device__ __forceinline__ void mma_tf32(float* c, const uint32_t* a, uint32_t b0, uint32_t b1) {
    asm volatile(
        "mma.sync.aligned.m16n8k8.row.col.f32.tf32.tf32.f32 "
        "{%0,%1,%2,%3}, {%4,%5,%6,%7}, {%8,%9}, {%0,%1,%2,%3};"
        : "+f"(c[0]), "+f"(c[1]), "+f"(c[2]), "+f"(c[3])
        : "r"(a[0]), "r"(a[1]), "r"(a[2]), "r"(a[3]), "r"(b0), "r"(b1));
}
__device__ __forceinline__ void ldsm_x4(uint32_t* d, uint32_t addr) {
    asm volatile("ldmatrix.sync.aligned.m8n8.x4.shared.b16 {%0,%1,%2,%3}, [%4];"
                 : "=r"(d[0]), "=r"(d[1]), "=r"(d[2]), "=r"(d[3]) : "r"(addr));
}

// ---------------- routing: scores + top-4 (R9 version) ----------------
__global__ void __launch_bounds__(256) k_score(const float* __restrict__ x,
                                               const float* __restrict__ sel) {
    __shared__ float Xs[32][36];
    __shared__ float Bs[32][36];
    __shared__ float Ss[32][36];
    __shared__ int   scnt[EX];
    int tid = threadIdx.x;
    int n0 = blockIdx.x * 32;
    int trow = tid >> 3;
    int tc = (tid & 7) * 4;
    if (tid < EX) scnt[tid] = 0;
    if (tid < 32) g_tokcnt[n0 + tid] = 0;
    float acc[4] = {0.f, 0.f, 0.f, 0.f};

    for (int k0 = 0; k0 < DM; k0 += 32) {
        {
            int r = tid >> 3, c = (tid & 7) * 4;
            *(float4*)&Xs[r][c] = *(const float4*)(x + (size_t)(n0 + r) * DM + k0 + c);
        }
        {
            int e = tid >> 3, kk = (tid & 7) * 4;
            float4 v = *(const float4*)(sel + (size_t)e * DM + k0 + kk);
            Bs[kk][e] = v.x; Bs[kk + 1][e] = v.y; Bs[kk + 2][e] = v.z; Bs[kk + 3][e] = v.w;
        }
        __syncthreads();
#pragma unroll
        for (int kk = 0; kk < 32; kk++) {
            float a = Xs[trow][kk];
            float4 b = *(float4*)&Bs[kk][tc];
            acc[0] += a * b.x; acc[1] += a * b.y; acc[2] += a * b.z; acc[3] += a * b.w;
        }
        __syncthreads();
    }
    *(float4*)&Ss[trow][tc] = make_float4(acc[0], acc[1], acc[2], acc[3]);
    __syncthreads();

    if (tid < 32) {
        int n = n0 + tid;
        float s[EX];
#pragma unroll
        for (int e = 0; e < EX; e++) s[e] = Ss[tid][e];
        for (int k = 0; k < TOPK; k++) {
            float best = -INFINITY; int bi = 0;
#pragma unroll
            for (int e = 0; e < EX; e++)
                if (s[e] > best) { best = s[e]; bi = e; }
            s[bi] = -INFINITY;
            g_route_e[n * TOPK + k] = bi;
            g_route_g[n * TOPK + k] = 1.f / (1.f + expf(-best));
            atomicAdd(&scnt[bi], 1);
        }
    }
    __syncthreads();
    if (tid < EX) g_bcnt[blockIdx.x * EX + tid] = scnt[tid];
}

// ---------------- scan ----------------
__global__ void k_scan() {
    int lane = threadIdx.x;
    int tot = 0;
    for (int b = 0; b < NBLK; b++) tot += g_bcnt[b * EX + lane];
    int s = tot;
#pragma unroll
    for (int off = 1; off < 32; off <<= 1) {
        int v = __shfl_up_sync(0xffffffffu, s, off);
        if (lane >= off) s += v;
    }
    int excl = s - tot;
    g_offsets[lane] = excl;
    if (lane == EX - 1) g_offsets[EX] = s;
    int run = excl;
    for (int b = 0; b < NBLK; b++) {
        g_fillbase[b * EX + lane] = run;
        run += g_bcnt[b * EX + lane];
    }
}

// ---------------- fill ----------------
__global__ void __launch_bounds__(128) k_fill() {
    __shared__ int sbase[EX], scnt[EX];
    int tid = threadIdx.x;
    if (tid < 32) {
        sbase[tid] = g_fillbase[blockIdx.x * EX + tid];
        scnt[tid] = 0;
    }
    __syncthreads();
    int t = blockIdx.x * 128 + tid;
    int e = g_route_e[t];
    int lp = atomicAdd(&scnt[e], 1);
    int p = sbase[e] + lp;
    g_perm_nk[p] = t;
    g_perm_g[p] = g_route_g[t];
}

// ---------------- expert MLP: MT=64, 512 threads (16 warps), tf32 + ldmatrix ----------------
#define AS 36
#define BS 136
#define HS 132
#define OFF_A 0                         // 2*64*36*4  = 18432
#define OFF_B 18432                     // 2*32*136*4 = 34816
#define OFF_H 53248                     // 64*132*4   = 33792
#define OFF_NK   87040
#define OFF_NROW 87296
#define OFF_GATE 87552
#define SMEM_EXPERT 87808

__global__ void __launch_bounds__(512, 2) k_expert(const float* __restrict__ x,
                                                   const float* __restrict__ w1,
                                                   const float* __restrict__ w2,
                                                   float* __restrict__ y) {
    extern __shared__ char sm[];
    __shared__ int winners[MT];
    __shared__ int nwin;
    int tid = threadIdx.x, lane = tid & 31, wid = tid >> 5;
    int e = blockIdx.y;

    int off0 = g_offsets[e], off1 = g_offsets[e + 1];
    int base = off0 + blockIdx.x * MT;
    if (base >= off1) return;
    int cnt = min(MT, off1 - base);

    int wm = wid & 3, wn = wid >> 2;     // 4x4 warp grid: 16-row x 32-col tiles
    float* As0 = (float*)(sm + OFF_A);
    float* Bs0 = (float*)(sm + OFF_B);
    float* Hsm = (float*)(sm + OFF_H);
    int*   nks   = (int*)(sm + OFF_NK);
    int*   nrow  = (int*)(sm + OFF_NROW);
    float* gates = (float*)(sm + OFF_GATE);
    if (tid == 0) nwin = 0;
    if (tid < MT) {
        if (tid < cnt) {
            int nk = g_perm_nk[base + tid];
            nks[tid] = nk; nrow[tid] = nk >> 2; gates[tid] = g_perm_g[base + tid];
        } else {
            nks[tid] = 0; nrow[tid] = 0; gates[tid] = 0.f;
        }
    }
    __syncthreads();

    const float* w1e = w1 + (size_t)e * DM * HH;   // [D,H]
    const float* w2e = w2 + (size_t)e * HH * DM;   // [H,D]

    int g = lane >> 2, t4 = lane & 3;
    int mrow0 = wm * 16, ncol0 = wn * 32;
    int Lrow = (lane & 7) + ((lane >> 3) & 1) * 8;
    int Lcol = (lane >> 4) * 4;

    uint32_t smb_A = smem_u32(As0);
    uint32_t smb_H = smem_u32(Hsm);

    // staging coords (512 threads)
    int ar0 = tid >> 3, ac0 = (tid & 7) * 4;       // A: 64x32, 1 float4/thread
    int br0 = tid >> 5, bc0 = (tid & 31) * 4;      // B: 32x128, 2 float4/thread (rows br0, br0+16)
    const float* pA = x + (size_t)nrow[ar0] * DM + ac0;

    float4 ra, rb[2];

    // ---- GEMM1: H[64,128] = X[64,512] * W1[512,128], 16 chunks of K=32 ----
    float c1[4][4];
#pragma unroll
    for (int ni = 0; ni < 4; ni++)
#pragma unroll
        for (int j = 0; j < 4; j++) c1[ni][j] = 0.f;

    ra = *(const float4*)pA;
#pragma unroll
    for (int i = 0; i < 2; i++)
        rb[i] = *(const float4*)(w1e + (size_t)(br0 + 16 * i) * HH + bc0);
    {
        *(float4*)&As0[ar0 * AS + ac0] = round4(ra);
#pragma unroll
        for (int i = 0; i < 2; i++)
            *(float4*)&Bs0[(br0 + 16 * i) * BS + bc0] = round4(rb[i]);
    }
    __syncthreads();

    int p = 0;
    for (int kc = 0; kc < 16; kc++) {
        if (kc < 15) {
            int k0 = (kc + 1) * 32;
            ra = *(const float4*)(pA + k0);
#pragma unroll
            for (int i = 0; i < 2; i++)
                rb[i] = *(const float4*)(w1e + (size_t)(k0 + br0 + 16 * i) * HH + bc0);
        }
        uint32_t aBase = smb_A + (uint32_t)(p * 64 * AS) * 4;
        const float* Bsh = Bs0 + p * 32 * BS;
#pragma unroll
        for (int ks = 0; ks < 4; ks++) {
            int kk = ks * 8;
            uint32_t a[4];
            ldsm_x4(a, aBase + (uint32_t)((mrow0 + Lrow) * AS + Lcol + kk) * 4);
#pragma unroll
            for (int ni = 0; ni < 4; ni++) {
                int n = ncol0 + ni * 8;
                uint32_t b0 = __float_as_uint(Bsh[(kk + t4) * BS + n + g]);
                uint32_t b1 = __float_as_uint(Bsh[(kk + t4 + 4) * BS + n + g]);
                mma_tf32(c1[ni], a, b0, b1);
            }
        }
        if (kc < 15) {
            float* Asn = As0 + (1 - p) * 64 * AS;
            float* Bsn = Bs0 + (1 - p) * 32 * BS;
            *(float4*)&Asn[ar0 * AS + ac0] = round4(ra);
#pragma unroll
            for (int i = 0; i < 2; i++)
                *(float4*)&Bsn[(br0 + 16 * i) * BS + bc0] = round4(rb[i]);
        }
        __syncthreads();
        p ^= 1;
    }

    // ---- H = tf32(relu(.)*gate) -> SMEM [64m][128k] ----
    {
        int rA = mrow0 + g;
        float gA = gates[rA], gB = gates[rA + 8];
#pragma unroll
        for (int ni = 0; ni < 4; ni++) {
            int col = ncol0 + ni * 8 + t4 * 2;
            float2 hA, hB;
            hA.x = to_tf32(fmaxf(c1[ni][0], 0.f) * gA);
            hA.y = to_tf32(fmaxf(c1[ni][1], 0.f) * gA);
            hB.x = to_tf32(fmaxf(c1[ni][2], 0.f) * gB);
            hB.y = to_tf32(fmaxf(c1[ni][3], 0.f) * gB);
            *(float2*)&Hsm[rA * HS + col] = hA;
            *(float2*)&Hsm[(rA + 8) * HS + col] = hB;
        }
    }
    __syncthreads();

    // ---- GEMM2: Y[64,512] = H[64,128] * W2[128,512]; 16 chunks = (v, kch) ----
    float c2[4][4];
#pragma unroll
    for (int ni = 0; ni < 4; ni++)
#pragma unroll
        for (int j = 0; j < 4; j++) c2[ni][j] = 0.f;

#pragma unroll
    for (int i = 0; i < 2; i++)
        rb[i] = *(const float4*)(w2e + (size_t)(br0 + 16 * i) * DM + bc0);
    {
#pragma unroll
        for (int i = 0; i < 2; i++)
            *(float4*)&Bs0[(br0 + 16 * i) * BS + bc0] = round4(rb[i]);
    }
    __syncthreads();

    p = 0;
    for (int c = 0; c < 16; c++) {
        int v = c >> 2, kch = c & 3;
        if (c < 15) {
            int vn = (c + 1) >> 2, kn = (c + 1) & 3;
#pragma unroll
            for (int i = 0; i < 2; i++)
                rb[i] = *(const float4*)(w2e + (size_t)(kn * 32 + br0 + 16 * i) * DM +
                                         vn * 128 + bc0);
        }
        const float* Bsh = Bs0 + p * 32 * BS;
#pragma unroll
        for (int ks = 0; ks < 4; ks++) {
            int kh = kch * 32 + ks * 8;
            int kk = ks * 8;
            uint32_t a[4];
            ldsm_x4(a, smb_H + (uint32_t)((mrow0 + Lrow) * HS + Lcol + kh) * 4);
#pragma unroll
            for (int ni = 0; ni < 4; ni++) {
                int n = ncol0 + ni * 8;
                uint32_t b0 = __float_as_uint(Bsh[(kk + t4) * BS + n + g]);
                uint32_t b1 = __float_as_uint(Bsh[(kk + t4 + 4) * BS + n + g]);
                mma_tf32(c2[ni], a, b0, b1);
            }
        }
        if (c < 15) {
            float* Bsn = Bs0 + (1 - p) * 32 * BS;
#pragma unroll
            for (int i = 0; i < 2; i++)
                *(float4*)&Bsn[(br0 + 16 * i) * BS + bc0] = round4(rb[i]);
        }
        __syncthreads();
        p ^= 1;

        if (kch == 3) {
            int v0 = v * 128;
            int rA = mrow0 + g;
            int rB = rA + 8;
#pragma unroll
            for (int ni = 0; ni < 4; ni++) {
                int col = v0 + ncol0 + ni * 8 + t4 * 2;
                if (rA < cnt) {
                    float2 o0; o0.x = c2[ni][0]; o0.y = c2[ni][1];
                    *(float2*)(g_buf + (size_t)nks[rA] * DM + col) = o0;
                }
                if (rB < cnt) {
                    float2 o1; o1.x = c2[ni][2]; o1.y = c2[ni][3];
                    *(float2*)(g_buf + (size_t)nks[rB] * DM + col) = o1;
                }
                c2[ni][0] = 0.f; c2[ni][1] = 0.f;
                c2[ni][2] = 0.f; c2[ni][3] = 0.f;
            }
        }
    }

    // ---- fused reduce: last completer sums a token's 4 partials ----
    __syncthreads();
    __threadfence();
    if (tid < cnt) {
        int n = nrow[tid];
        int old = atomicAdd(&g_tokcnt[n], 1);
        if (old == 3) {
            int w = atomicAdd(&nwin, 1);
            winners[w] = n;
        }
    }
    __syncthreads();
    __threadfence();
    int nw = nwin;
    const float4* bb = (const float4*)g_buf;
    for (int i = tid; i < nw * 128; i += 512) {
        int n = winners[i >> 7], v4 = i & 127;
        size_t b0 = (size_t)(n * 4) * 128 + v4;
        float4 r0 = bb[b0];
        float4 r1 = bb[b0 + 128];
        float4 r2 = bb[b0 + 256];
        float4 r3 = bb[b0 + 384];
        float4 o;
        o.x = (r0.x + r1.x) + (r2.x + r3.x);
        o.y = (r0.y + r1.y) + (r2.y + r3.y);
        o.z = (r0.z + r1.z) + (r2.z + r3.z);
        o.w = (r0.w + r1.w) + (r2.w + r3.w);
        ((float4*)y)[(size_t)n * 128 + v4] = o;
    }
}

extern "C" void kernel_launch(void* const* d_in, const int* in_sizes, int n_in,
                              void* d_out, int out_size) {
    const float* x   = (const float*)d_in[0];
    const float* sel = (const float*)d_in[1];
    const float* w1  = (const float*)d_in[2];
    const float* w2  = (const float*)d_in[3];
    float* y = (float*)d_out;

    cudaFuncSetAttribute(k_expert, cudaFuncAttributeMaxDynamicSharedMemorySize, SMEM_EXPERT);

    k_score<<<NBLK, 256>>>(x, sel);
    k_scan<<<1, 32>>>();
    k_fill<<<NBLK, 128>>>();
    k_expert<<<dim3(16, EX), 512, SMEM_EXPERT>>>(x, w1, w2, y);
}